// round 16
// baseline (speedup 1.0000x reference)
#include <cuda_runtime.h>
#include <cuda_bf16.h>
#include <math.h>
#include <stdint.h>

// ---------------- problem constants ----------------
#define B_    4
#define S_    2048
#define D_    1024
#define H_    16
#define DH    64
#define DHR   32
#define DLAT  512
#define MS    (B_*S_)
#define DQK   96

typedef uint32_t u32;
typedef uint64_t u64;
typedef unsigned short u16;

// ---------------- packed weight offsets ----------------
#define OFF_DOWN   0
#define OFF_UQQR   1081344
#define OFF_UKUV   1867776
#define OFF_WO     2916352
#define WTOT       3964928

// ---------------- scratch ----------------
__device__ __align__(16) u16 g_xh [MS*D_],  g_xl [MS*D_];
__device__ __align__(16) u16 g_wh [WTOT],   g_wl [WTOT];
__device__ __align__(16) u16 g_cQKVh[MS*D_], g_cQKVl[MS*D_];
__device__ __align__(16) u16 g_vh [MS*D_],  g_vl [MS*D_];
__device__ __align__(16) u16 g_qh [(size_t)B_*H_*S_*DQK], g_ql[(size_t)B_*H_*S_*DQK];
__device__ __align__(16) u16 g_kh [(size_t)B_*H_*S_*DQK], g_kl[(size_t)B_*H_*S_*DQK];
__device__ __align__(16) u16 g_ah [MS*D_],  g_al [MS*D_];
__device__ __align__(16) float2 g_rope[S_*16];

// ---------------- helpers ----------------
__device__ __forceinline__ unsigned sptr(const void* p) {
    return (unsigned)__cvta_generic_to_shared(p);
}
__device__ __forceinline__ void ldmx4(u32* r, unsigned a) {
    asm volatile("ldmatrix.sync.aligned.m8n8.x4.shared.b16 {%0,%1,%2,%3},[%4];"
        : "=r"(r[0]), "=r"(r[1]), "=r"(r[2]), "=r"(r[3]) : "r"(a));
}
__device__ __forceinline__ void ldmx4t(u32* r, unsigned a) {
    asm volatile("ldmatrix.sync.aligned.m8n8.x4.trans.shared.b16 {%0,%1,%2,%3},[%4];"
        : "=r"(r[0]), "=r"(r[1]), "=r"(r[2]), "=r"(r[3]) : "r"(a));
}
__device__ __forceinline__ void mma16816(float* c, const u32* a, u32 b0, u32 b1) {
    asm volatile("mma.sync.aligned.m16n8k16.row.col.f32.bf16.bf16.f32 "
        "{%0,%1,%2,%3},{%4,%5,%6,%7},{%8,%9},{%0,%1,%2,%3};"
        : "+f"(c[0]), "+f"(c[1]), "+f"(c[2]), "+f"(c[3])
        : "r"(a[0]), "r"(a[1]), "r"(a[2]), "r"(a[3]), "r"(b0), "r"(b1));
}
__device__ __forceinline__ void split_pack(float a, float b, u32& hi, u32& lo) {
    __nv_bfloat16 ha = __float2bfloat16(a), hb = __float2bfloat16(b);
    __nv_bfloat162 hh; hh.x = ha; hh.y = hb;
    hi = *(u32*)&hh;
    __nv_bfloat162 ll;
    ll.x = __float2bfloat16(a - __bfloat162float(ha));
    ll.y = __float2bfloat16(b - __bfloat162float(hb));
    lo = *(u32*)&ll;
}
__device__ __forceinline__ void cpa16(u32 d, const void* s) {
    asm volatile("cp.async.ca.shared.global [%0], [%1], 16;" :: "r"(d), "l"(s));
}
__device__ __forceinline__ void cpa16z(u32 d, const void* s, int sz) {
    asm volatile("cp.async.ca.shared.global [%0], [%1], 16, %2;"
                 :: "r"(d), "l"(s), "r"(sz));
}
__device__ __forceinline__ void cp_commit() {
    asm volatile("cp.async.commit_group;" ::: "memory");
}

// ---------------- RoPE table ----------------
__global__ __launch_bounds__(256) void rope_table()
{
    int i = blockIdx.x * 256 + threadIdx.x;
    if (i >= S_ * 16) return;
    int s = i >> 4, t = i & 15;
    double inv = pow(10000.0, -(double)(2 * t) / (double)DHR);
    double ang = (double)s * inv;
    g_rope[i] = make_float2((float)cos(ang), (float)sin(ang));
}

// ---------------- merged split ----------------
#define NSPLIT 9
struct SplitArgs {
    const float* src[NSPLIT];
    u16* dh[NSPLIT];
    u16* dl[NSPLIT];
    int  n4[NSPLIT];
    int  cumblk[NSPLIT + 1];
};

__global__ __launch_bounds__(256) void splitall(SplitArgs a)
{
    int blk = blockIdx.x;
    int r = 0;
    #pragma unroll
    for (int i = 1; i < NSPLIT; i++) if (blk >= a.cumblk[i]) r = i;
    int i4 = (blk - a.cumblk[r]) * 256 + threadIdx.x;
    if (i4 >= a.n4[r]) return;
    float4 v = ((const float4*)a.src[r])[i4];
    u32 h0, l0, h1, l1;
    split_pack(v.x, v.y, h0, l0);
    split_pack(v.z, v.w, h1, l1);
    ((uint2*)a.dh[r])[i4] = make_uint2(h0, h1);
    ((uint2*)a.dl[r])[i4] = make_uint2(l0, l1);
}

// ---------------- epilogue store modes ----------------
__device__ __forceinline__ void store_region(
    int mode, float v0, float v1, int r0, int col,
    float* F, u16* Hp, u16* Lp, int ld)
{
    if (mode == 0) {
        *(float2*)&F[(size_t)r0 * ld + col] = make_float2(v0, v1);
    } else if (mode == 1) {
        u32 h, l;
        split_pack(v0, v1, h, l);
        *(u32*)&Hp[(size_t)r0 * ld + col] = h;
        *(u32*)&Lp[(size_t)r0 * ld + col] = l;
    } else {
        const int b = r0 >> 11, s = r0 & 2047;
        if (mode == 2) {
            int hh = col >> 6, d = col & 63;
            size_t dst = ((size_t)(b * H_ + hh) * S_ + s) * DQK + d;
            u32 h, l;
            split_pack(v0, v1, h, l);
            *(u32*)&Hp[dst] = h;
            *(u32*)&Lp[dst] = l;
        } else if (mode == 3) {
            int hh = col >> 5, t2 = col & 31;
            float2 cs = g_rope[s * 16 + (t2 >> 1)];
            float o0 = v0 * cs.x - v1 * cs.y;
            float o1 = v0 * cs.y + v1 * cs.x;
            size_t dst = ((size_t)(b * H_ + hh) * S_ + s) * DQK + DH + t2;
            u32 h, l;
            split_pack(o0, o1, h, l);
            *(u32*)&Hp[dst] = h;
            *(u32*)&Lp[dst] = l;
        } else {
            float2 cs = g_rope[s * 16 + (col >> 1)];
            float o0 = v0 * cs.x - v1 * cs.y;
            float o1 = v0 * cs.y + v1 * cs.x;
            u32 h, l;
            split_pack(o0, o1, h, l);
            #pragma unroll
            for (int hh = 0; hh < H_; hh++) {
                size_t dst = ((size_t)(b * H_ + hh) * S_ + s) * DQK + DH + col;
                *(u32*)&Hp[dst] = h;
                *(u32*)&Lp[dst] = l;
            }
        }
    }
}

// ---------------- split-bf16 GEMM (128x128, 2 CTA/SM) ----------------------
// rowoff: global row offset added in epilogue addressing (for batch-chunk WO).
#define GBM 128
#define GBN 128
#define GBK 32
#define GP  40
#define GT  (GBM*GP)
#define GSTAGE (4*GT)
#define GEMM_DSMEM (2*GSTAGE*2)

__global__ __launch_bounds__(256, 2) void gemm_cp(
    const u16* __restrict__ Ah, const u16* __restrict__ Al, int lda,
    const u16* __restrict__ Bh, const u16* __restrict__ Bl,
    int mode0, float* F0, u16* H0, u16* L0, int ld0,
    int mode1, float* F1, u16* H1, u16* L1, int ld1,
    int NS, int M, int N, int K, int rowoff)
{
    extern __shared__ __align__(16) u16 gsm[];
    const int tid = threadIdx.x, lane = tid & 31, wid = tid >> 5;
    const int bm = blockIdx.y * GBM, bn = blockIdx.x * GBN;
    const int wm = (wid & 3) * 32, wn = (wid >> 2) * 64;
    const int g = lane >> 2, t = lane & 3;
    const int nst = K / GBK;

    float acc[2][8][4];
    #pragma unroll
    for (int mi = 0; mi < 2; mi++)
        #pragma unroll
        for (int nj = 0; nj < 8; nj++)
            #pragma unroll
            for (int c = 0; c < 4; c++) acc[mi][nj][c] = 0.f;

    auto load_stage = [&](int s) {
        u16* sb = gsm + (s & 1) * GSTAGE;
        const int k0 = s * GBK;
        #pragma unroll
        for (int i = tid; i < 512; i += 256) {
            int r = i >> 2, c = i & 3;
            int so = r * GP + c * 8;
            size_t ga = (size_t)(bm + r) * lda + k0 + c * 8;
            cpa16(sptr(sb + so),      Ah + ga);
            cpa16(sptr(sb + GT + so), Al + ga);
            int br = bn + r;
            int ok = (br < N) ? 16 : 0;
            size_t gb = (size_t)(ok ? br : 0) * K + k0 + c * 8;
            cpa16z(sptr(sb + 2*GT + so), Bh + gb, ok);
            cpa16z(sptr(sb + 3*GT + so), Bl + gb, ok);
        }
        cp_commit();
    };

    load_stage(0);
    if (nst > 1) load_stage(1);

    for (int s = 0; s < nst; s++) {
        if (s + 1 < nst) asm volatile("cp.async.wait_group 1;" ::: "memory");
        else             asm volatile("cp.async.wait_group 0;" ::: "memory");
        __syncthreads();

        u16* sb = gsm + (s & 1) * GSTAGE;
        #pragma unroll
        for (int kk = 0; kk < GBK; kk += 16) {
            u32 a[2][2][4];
            #pragma unroll
            for (int mi = 0; mi < 2; mi++) {
                int row = wm + mi * 16 + (lane & 15), col = kk + (lane >> 4) * 8;
                ldmx4(a[0][mi], sptr(sb + row*GP + col));
                ldmx4(a[1][mi], sptr(sb + GT + row*GP + col));
            }
            u32 bh[4][4], bl[4][4];
            #pragma unroll
            for (int ng = 0; ng < 4; ng++) {
                int row = wn + ng * 16 + (lane & 15), col = kk + (lane >> 4) * 8;
                ldmx4(bh[ng], sptr(sb + 2*GT + row*GP + col));
                ldmx4(bl[ng], sptr(sb + 3*GT + row*GP + col));
            }
            #pragma unroll
            for (int ng = 0; ng < 4; ng++)
                #pragma unroll
                for (int mi = 0; mi < 2; mi++) {
                    mma16816(acc[mi][2*ng],   a[0][mi], bh[ng][0], bh[ng][2]);
                    mma16816(acc[mi][2*ng+1], a[0][mi], bh[ng][1], bh[ng][3]);
                }
            #pragma unroll
            for (int ng = 0; ng < 4; ng++)
                #pragma unroll
                for (int mi = 0; mi < 2; mi++) {
                    mma16816(acc[mi][2*ng],   a[0][mi], bl[ng][0], bl[ng][2]);
                    mma16816(acc[mi][2*ng+1], a[0][mi], bl[ng][1], bl[ng][3]);
                }
            #pragma unroll
            for (int ng = 0; ng < 4; ng++)
                #pragma unroll
                for (int mi = 0; mi < 2; mi++) {
                    mma16816(acc[mi][2*ng],   a[1][mi], bh[ng][0], bh[ng][2]);
                    mma16816(acc[mi][2*ng+1], a[1][mi], bh[ng][1], bh[ng][3]);
                }
        }
        __syncthreads();
        if (s + 2 < nst) load_stage(s + 2);
    }

    #pragma unroll
    for (int mi = 0; mi < 2; mi++) {
        int r0 = rowoff + bm + wm + mi * 16 + g;
        #pragma unroll
        for (int nj = 0; nj < 8; nj++) {
            int col = bn + wn + nj * 8 + t * 2;
            if (col >= N) continue;
            float v0 = acc[mi][nj][0], v1 = acc[mi][nj][1];
            float w0 = acc[mi][nj][2], w1 = acc[mi][nj][3];
            if (col < NS) {
                store_region(mode0, v0, v1, r0,     col, F0, H0, L0, ld0);
                store_region(mode0, w0, w1, r0 + 8, col, F0, H0, L0, ld0);
            } else {
                store_region(mode1, v0, v1, r0,     col - NS, F1, H1, L1, ld1);
                store_region(mode1, w0, w1, r0 + 8, col - NS, F1, H1, L1, ld1);
            }
        }
    }
}

// ---------------- flash attention (per-batch launch, log2 softmax) ---------
#define FBQ 256
#define FBK 64
#define QKP 104
#define VP  72
#define KVST (2*64*QKP + 2*64*VP)
#define FQ_U16 (2*FBQ*QKP)
#define FLASH_SMEM_U16 (FQ_U16 + 2*KVST)
#define FLASH_SMEM_BYTES (FLASH_SMEM_U16 * 2)

__global__ __launch_bounds__(512, 1) void flash_mma(
    const u16* __restrict__ Qh, const u16* __restrict__ Ql,
    const u16* __restrict__ Kh, const u16* __restrict__ Kl,
    const u16* __restrict__ Vh, const u16* __restrict__ Vl,
    u16* __restrict__ Oh, u16* __restrict__ Ol, int b)
{
    extern __shared__ __align__(16) u16 smf[];
    u16* Qsh = smf;
    u16* Qsl = smf + FBQ*QKP;

    const int h = blockIdx.y;
    const int bh = b * H_ + h;
    const int qb = gridDim.x - 1 - blockIdx.x;
    const int q0 = qb * FBQ;
    const int tid = threadIdx.x, w = tid >> 5, lane = tid & 31;
    const int g = lane >> 2, t = lane & 3;

    auto load_kv = [&](int kb) {
        u16* st = smf + FQ_U16 + (kb & 1) * KVST;
        const size_t kbase = ((size_t)bh * S_ + kb * FBK) * DQK;
        for (int c = tid; c < 64 * 12; c += 512) {
            int r = c / 12, s = c % 12;
            const size_t go = kbase + (size_t)r * DQK + s * 8;
            cpa16(sptr(st + r*QKP + s*8),            Kh + go);
            cpa16(sptr(st + 64*QKP + r*QKP + s*8),   Kl + go);
        }
        for (int c = tid; c < 64 * 8; c += 512) {
            int r = c >> 3, s = c & 7;
            size_t gv = ((size_t)(b * S_ + kb * FBK + r)) * D_ + h * DH + s * 8;
            cpa16(sptr(st + 2*64*QKP + r*VP + s*8),          Vh + gv);
            cpa16(sptr(st + 2*64*QKP + 64*VP + r*VP + s*8),  Vl + gv);
        }
        cp_commit();
    };

    {
        const size_t qbase = ((size_t)bh * S_ + q0) * DQK;
        for (int c = tid; c < FBQ * 12; c += 512) {
            int r = c / 12, s = c % 12;
            const size_t go = qbase + (size_t)r * DQK + s * 8;
            cpa16(sptr(Qsh + r*QKP + s*8), Qh + go);
            cpa16(sptr(Qsl + r*QKP + s*8), Ql + go);
        }
        load_kv(0);
    }

    float acco[8][4];
    #pragma unroll
    for (int j = 0; j < 8; j++)
        #pragma unroll
        for (int c = 0; c < 4; c++) acco[j][c] = 0.f;
    float mstate[2] = {-INFINITY, -INFINITY};
    float lstate[2] = {0.f, 0.f};
    const float scl2 = rsqrtf(96.f) * 1.4426950408889634f;
    const int qiA = q0 + w * 16 + g;
    const int qiB = qiA + 8;

    const int nkb = (q0 + FBQ) / FBK;
    for (int kb = 0; kb < nkb; kb++) {
        if (kb + 1 < nkb) {
            load_kv(kb + 1);
            asm volatile("cp.async.wait_group 1;" ::: "memory");
        } else {
            asm volatile("cp.async.wait_group 0;" ::: "memory");
        }
        __syncthreads();

        u16* st  = smf + FQ_U16 + (kb & 1) * KVST;
        u16* Ksh = st;
        u16* Ksl = st + 64*QKP;
        u16* Vsh = st + 2*64*QKP;
        u16* Vsl = st + 2*64*QKP + 64*VP;
        const int k0 = kb * FBK;

        const bool active = (k0 <= q0 + w * 16 + 15);
        if (active) {
            float sc[8][4];
            #pragma unroll
            for (int j = 0; j < 8; j++)
                #pragma unroll
                for (int c = 0; c < 4; c++) sc[j][c] = 0.f;

            #pragma unroll
            for (int kc = 0; kc < 6; kc++) {
                u32 ah[4], al[4];
                {
                    int row = w * 16 + (lane & 15), col = kc * 16 + (lane >> 4) * 8;
                    ldmx4(ah, sptr(&Qsh[row*QKP + col]));
                    ldmx4(al, sptr(&Qsl[row*QKP + col]));
                }
                u32 kh[4][4], kl[4][4];
                #pragma unroll
                for (int ng = 0; ng < 4; ng++) {
                    int row = ng * 16 + (lane & 15), col = kc * 16 + (lane >> 4) * 8;
                    ldmx4(kh[ng], sptr(&Ksh[row*QKP + col]));
                    ldmx4(kl[ng], sptr(&Ksl[row*QKP + col]));
                }
                #pragma unroll
                for (int ng = 0; ng < 4; ng++) {
                    mma16816(sc[2*ng],   ah, kh[ng][0], kh[ng][2]);
                    mma16816(sc[2*ng+1], ah, kh[ng][1], kh[ng][3]);
                }
                #pragma unroll
                for (int ng = 0; ng < 4; ng++) {
                    mma16816(sc[2*ng],   ah, kl[ng][0], kl[ng][2]);
                    mma16816(sc[2*ng+1], ah, kl[ng][1], kl[ng][3]);
                }
                #pragma unroll
                for (int ng = 0; ng < 4; ng++) {
                    mma16816(sc[2*ng],   al, kh[ng][0], kh[ng][2]);
                    mma16816(sc[2*ng+1], al, kh[ng][1], kh[ng][3]);
                }
            }

            const bool diag = (k0 + FBK - 1 > q0 + w * 16);
            #pragma unroll
            for (int j = 0; j < 8; j++) {
                int kcol = k0 + j * 8 + t * 2;
                #pragma unroll
                for (int c = 0; c < 4; c++) {
                    int ki = kcol + (c & 1);
                    int qi = (c < 2) ? qiA : qiB;
                    float v = fminf(fmaxf(sc[j][c], -80.f), 80.f) * scl2;
                    sc[j][c] = (!diag || ki <= qi) ? v : -INFINITY;
                }
            }

            float mA = -INFINITY, mB = -INFINITY;
            #pragma unroll
            for (int j = 0; j < 8; j++) {
                mA = fmaxf(mA, fmaxf(sc[j][0], sc[j][1]));
                mB = fmaxf(mB, fmaxf(sc[j][2], sc[j][3]));
            }
            mA = fmaxf(mA, __shfl_xor_sync(0xffffffffu, mA, 1));
            mA = fmaxf(mA, __shfl_xor_sync(0xffffffffu, mA, 2));
            mB = fmaxf(mB, __shfl_xor_sync(0xffffffffu, mB, 1));
            mB = fmaxf(mB, __shfl_xor_sync(0xffffffffu, mB, 2));
            float mnA = fmaxf(mstate[0], mA), mnB = fmaxf(mstate[1], mB);
            float corrA = exp2f(mstate[0] - mnA);
            float corrB = exp2f(mstate[1] - mnB);
            float sumA = 0.f, sumB = 0.f;
            #pragma unroll
            for (int j = 0; j < 8; j++) {
                sc[j][0] = exp2f(sc[j][0] - mnA); sumA += sc[j][0];
                sc[j][1] = exp2f(sc[j][1] - mnA); sumA += sc[j][1];
                sc[j][2] = exp2f(sc[j][2] - mnB); sumB += sc[j][2];
                sc[j][3] = exp2f(sc[j][3] - mnB); sumB += sc[j][3];
            }
            sumA += __shfl_xor_sync(0xffffffffu, sumA, 1);
            sumA += __shfl_xor_sync(0xffffffffu, sumA, 2);
            sumB += __shfl_xor_sync(0xffffffffu, sumB, 1);
            sumB += __shfl_xor_sync(0xffffffffu, sumB, 2);
            lstate[0] = lstate[0] * corrA + sumA;
            lstate[1] = lstate[1] * corrB + sumB;
            mstate[0] = mnA; mstate[1] = mnB;
            #pragma unroll
            for (int vj = 0; vj < 8; vj++) {
                acco[vj][0] *= corrA; acco[vj][1] *= corrA;
                acco[vj][2] *= corrB; acco[vj][3] *= corrB;
            }

            #pragma unroll
            for (int kcp = 0; kcp < 4; kcp++) {
                u32 ph[4], pl[4];
                split_pack(sc[2*kcp  ][0], sc[2*kcp  ][1], ph[0], pl[0]);
                split_pack(sc[2*kcp  ][2], sc[2*kcp  ][3], ph[1], pl[1]);
                split_pack(sc[2*kcp+1][0], sc[2*kcp+1][1], ph[2], pl[2]);
                split_pack(sc[2*kcp+1][2], sc[2*kcp+1][3], ph[3], pl[3]);
                u32 vhf[4][4], vlf[4][4];
                #pragma unroll
                for (int vg = 0; vg < 4; vg++) {
                    int row = kcp * 16 + (lane & 15), col = vg * 16 + (lane >> 4) * 8;
                    ldmx4t(vhf[vg], sptr(&Vsh[row*VP + col]));
                    ldmx4t(vlf[vg], sptr(&Vsl[row*VP + col]));
                }
                #pragma unroll
                for (int vg = 0; vg < 4; vg++) {
                    mma16816(acco[2*vg],   ph, vhf[vg][0], vhf[vg][1]);
                    mma16816(acco[2*vg+1], ph, vhf[vg][2], vhf[vg][3]);
                }
                #pragma unroll
                for (int vg = 0; vg < 4; vg++) {
                    mma16816(acco[2*vg],   ph, vlf[vg][0], vlf[vg][1]);
                    mma16816(acco[2*vg+1], ph, vlf[vg][2], vlf[vg][3]);
                }
                #pragma unroll
                for (int vg = 0; vg < 4; vg++) {
                    mma16816(acco[2*vg],   pl, vhf[vg][0], vhf[vg][1]);
                    mma16816(acco[2*vg+1], pl, vhf[vg][2], vhf[vg][3]);
                }
            }
        }
        __syncthreads();
    }

    float ilA = 1.f / lstate[0], ilB = 1.f / lstate[1];
    int rA = b * S_ + q0 + w * 16 + g;
    #pragma unroll
    for (int vj = 0; vj < 8; vj++) {
        int col = h * DH + vj * 8 + t * 2;
        u32 h0, l0, h1, l1;
        split_pack(acco[vj][0] * ilA, acco[vj][1] * ilA, h0, l0);
        split_pack(acco[vj][2] * ilB, acco[vj][3] * ilB, h1, l1);
        *(u32*)&Oh[(size_t)rA * D_ + col] = h0;
        *(u32*)&Ol[(size_t)rA * D_ + col] = l0;
        *(u32*)&Oh[(size_t)(rA+8) * D_ + col] = h1;
        *(u32*)&Ol[(size_t)(rA+8) * D_ + col] = l1;
    }
}

// ---------------- launch ----------------
extern "C" void kernel_launch(void* const* d_in, const int* in_sizes, int n_in,
                              void* d_out, int out_size)
{
    const float* x     = (const float*)d_in[0];
    const float* W_DQ  = (const float*)d_in[1];
    const float* W_UQ  = (const float*)d_in[2];
    const float* W_QR  = (const float*)d_in[3];
    const float* W_DKV = (const float*)d_in[4];
    const float* W_UK  = (const float*)d_in[5];
    const float* W_UV  = (const float*)d_in[6];
    const float* W_KR  = (const float*)d_in[7];
    const float* W_O   = (const float*)d_in[8];
    float* out = (float*)d_out;

    u16 *xh,*xl,*wh,*wl,*ch,*cl,*vh,*vl,*qh,*ql,*kh,*kl,*ah,*al;
    cudaGetSymbolAddress((void**)&xh, g_xh);    cudaGetSymbolAddress((void**)&xl, g_xl);
    cudaGetSymbolAddress((void**)&wh, g_wh);    cudaGetSymbolAddress((void**)&wl, g_wl);
    cudaGetSymbolAddress((void**)&ch, g_cQKVh); cudaGetSymbolAddress((void**)&cl, g_cQKVl);
    cudaGetSymbolAddress((void**)&vh, g_vh);    cudaGetSymbolAddress((void**)&vl, g_vl);
    cudaGetSymbolAddress((void**)&qh, g_qh);    cudaGetSymbolAddress((void**)&ql, g_ql);
    cudaGetSymbolAddress((void**)&kh, g_kh);    cudaGetSymbolAddress((void**)&kl, g_kl);
    cudaGetSymbolAddress((void**)&ah, g_ah);    cudaGetSymbolAddress((void**)&al, g_al);

    static cudaStream_t s2 = nullptr;
    static cudaEvent_t evFork = nullptr, evJoin = nullptr;
    static cudaEvent_t evFl[B_] = {nullptr, nullptr, nullptr, nullptr};
    static cudaEvent_t evWO = nullptr;
    static int configured = 0;
    if (!configured) {
        cudaFuncSetAttribute(flash_mma, cudaFuncAttributeMaxDynamicSharedMemorySize,
                             FLASH_SMEM_BYTES);
        cudaFuncSetAttribute(gemm_cp, cudaFuncAttributeMaxDynamicSharedMemorySize,
                             GEMM_DSMEM);
        cudaStreamCreateWithFlags(&s2, cudaStreamNonBlocking);
        cudaEventCreateWithFlags(&evFork, cudaEventDisableTiming);
        cudaEventCreateWithFlags(&evJoin, cudaEventDisableTiming);
        cudaEventCreateWithFlags(&evWO,   cudaEventDisableTiming);
        for (int i = 0; i < B_; i++)
            cudaEventCreateWithFlags(&evFl[i], cudaEventDisableTiming);
        configured = 1;
    }

    // ---- split all fp32 inputs (one launch, main stream) ----
    SplitArgs sa;
    {
        const float* srcs[NSPLIT] = {x, W_DQ, W_DKV, W_KR, W_UQ, W_QR, W_UK, W_UV, W_O};
        u16* dhs[NSPLIT] = {xh, wh+OFF_DOWN, wh+OFF_DOWN+524288, wh+OFF_DOWN+1048576,
                            wh+OFF_UQQR, wh+OFF_UQQR+524288,
                            wh+OFF_UKUV, wh+OFF_UKUV+524288, wh+OFF_WO};
        u16* dls[NSPLIT] = {xl, wl+OFF_DOWN, wl+OFF_DOWN+524288, wl+OFF_DOWN+1048576,
                            wl+OFF_UQQR, wl+OFF_UQQR+524288,
                            wl+OFF_UKUV, wl+OFF_UKUV+524288, wl+OFF_WO};
        const int ns[NSPLIT] = {MS*D_, DLAT*D_, DLAT*D_, DHR*D_,
                                D_*DLAT, H_*DHR*DLAT, D_*DLAT, D_*DLAT, D_*D_};
        int cum = 0;
        for (int i = 0; i < NSPLIT; i++) {
            sa.src[i] = srcs[i]; sa.dh[i] = dhs[i]; sa.dl[i] = dls[i];
            sa.n4[i] = ns[i] / 4;
            sa.cumblk[i] = cum;
            cum += (sa.n4[i] + 255) / 256;
        }
        sa.cumblk[NSPLIT] = cum;
        splitall<<<cum, 256>>>(sa);
    }

    rope_table<<<(S_ * 16 + 255) / 256, 256>>>();

    auto gemm = [&](cudaStream_t st,
                    const u16* Ahp, const u16* Alp, int lda,
                    const u16* Bhp, const u16* Blp,
                    int m0, float* F0, u16* H0, u16* L0, int ld0,
                    int m1, float* F1, u16* H1, u16* L1, int ld1,
                    int NSv, int M, int N, int K, int rowoff) {
        gemm_cp<<<dim3((N + GBN - 1) / GBN, M / GBM), 256, GEMM_DSMEM, st>>>(
            Ahp, Alp, lda, Bhp, Blp, m0, F0, H0, L0, ld0,
            m1, F1, H1, L1, ld1, NSv, M, N, K, rowoff);
    };

    // DOWN (x -> cQKV, KR+rope -> k) — profiled slot (idx 3)
    gemm(0, xh, xl, D_, wh+OFF_DOWN, wl+OFF_DOWN,
         1, nullptr, ch, cl, D_,
         4, nullptr, kh, kl, 0,
         D_, MS, D_ + DHR, D_, 0);

    // fork: UQQR on s2, UKUV on main (concurrent)
    cudaEventRecord(evFork, 0);
    cudaStreamWaitEvent(s2, evFork, 0);

    gemm(0, ch + DLAT, cl + DLAT, D_, wh+OFF_UKUV, wl+OFF_UKUV,
         2, nullptr, kh, kl, 0,
         1, nullptr, vh, vl, D_,
         D_, MS, 2 * D_, DLAT, 0);

    gemm(s2, ch, cl, D_, wh+OFF_UQQR, wl+OFF_UQQR,
         2, nullptr, qh, ql, 0,
         3, nullptr, qh, ql, 0,
         D_, MS, D_ + H_ * DHR, DLAT, 0);

    cudaEventRecord(evJoin, s2);
    cudaStreamWaitEvent(0, evJoin, 0);

    // flash per batch on main; WO chunk per batch on s2, pipelined
    for (int b = 0; b < B_; b++) {
        flash_mma<<<dim3(S_ / FBQ, H_), dim3(512), FLASH_SMEM_BYTES>>>(
            qh, ql, kh, kl, vh, vl, ah, al, b);
        cudaEventRecord(evFl[b], 0);
        cudaStreamWaitEvent(s2, evFl[b], 0);
        gemm(s2, ah + (size_t)b * S_ * D_, al + (size_t)b * S_ * D_, D_,
             wh+OFF_WO, wl+OFF_WO,
             0, out, nullptr, nullptr, D_,
             0, out, nullptr, nullptr, D_,
             D_, S_, D_, D_, b * S_);
    }
    cudaEventRecord(evWO, s2);
    cudaStreamWaitEvent(0, evWO, 0);
}

// round 17
// speedup vs baseline: 1.3585x; 1.3585x over previous
#include <cuda_runtime.h>
#include <cuda_bf16.h>
#include <math.h>
#include <stdint.h>

// ---------------- problem constants ----------------
#define B_    4
#define S_    2048
#define D_    1024
#define H_    16
#define DH    64
#define DHR   32
#define DLAT  512
#define MS    (B_*S_)
#define DQK   96

typedef uint32_t u32;
typedef uint64_t u64;
typedef unsigned short u16;

// ---------------- packed weight offsets ----------------
#define OFF_DOWN   0
#define OFF_UQQR   1081344
#define OFF_UKUV   1867776
#define OFF_WO     2916352
#define WTOT       3964928

// ---------------- scratch ----------------
__device__ __align__(16) u16 g_xh [MS*D_],  g_xl [MS*D_];
__device__ __align__(16) u16 g_wh [WTOT],   g_wl [WTOT];
__device__ __align__(16) u16 g_cQKVh[MS*D_], g_cQKVl[MS*D_];
__device__ __align__(16) u16 g_vh [MS*D_],  g_vl [MS*D_];
__device__ __align__(16) u16 g_qh [(size_t)B_*H_*S_*DQK], g_ql[(size_t)B_*H_*S_*DQK];
__device__ __align__(16) u16 g_kh [(size_t)B_*H_*S_*DQK], g_kl[(size_t)B_*H_*S_*DQK];
__device__ __align__(16) u16 g_ah [MS*D_],  g_al [MS*D_];
__device__ __align__(16) float2 g_rope[S_*16];

// ---------------- helpers ----------------
__device__ __forceinline__ unsigned sptr(const void* p) {
    return (unsigned)__cvta_generic_to_shared(p);
}
__device__ __forceinline__ void ldmx4(u32* r, unsigned a) {
    asm volatile("ldmatrix.sync.aligned.m8n8.x4.shared.b16 {%0,%1,%2,%3},[%4];"
        : "=r"(r[0]), "=r"(r[1]), "=r"(r[2]), "=r"(r[3]) : "r"(a));
}
__device__ __forceinline__ void ldmx4t(u32* r, unsigned a) {
    asm volatile("ldmatrix.sync.aligned.m8n8.x4.trans.shared.b16 {%0,%1,%2,%3},[%4];"
        : "=r"(r[0]), "=r"(r[1]), "=r"(r[2]), "=r"(r[3]) : "r"(a));
}
__device__ __forceinline__ void mma16816(float* c, const u32* a, u32 b0, u32 b1) {
    asm volatile("mma.sync.aligned.m16n8k16.row.col.f32.bf16.bf16.f32 "
        "{%0,%1,%2,%3},{%4,%5,%6,%7},{%8,%9},{%0,%1,%2,%3};"
        : "+f"(c[0]), "+f"(c[1]), "+f"(c[2]), "+f"(c[3])
        : "r"(a[0]), "r"(a[1]), "r"(a[2]), "r"(a[3]), "r"(b0), "r"(b1));
}
__device__ __forceinline__ void split_pack(float a, float b, u32& hi, u32& lo) {
    __nv_bfloat16 ha = __float2bfloat16(a), hb = __float2bfloat16(b);
    __nv_bfloat162 hh; hh.x = ha; hh.y = hb;
    hi = *(u32*)&hh;
    __nv_bfloat162 ll;
    ll.x = __float2bfloat16(a - __bfloat162float(ha));
    ll.y = __float2bfloat16(b - __bfloat162float(hb));
    lo = *(u32*)&ll;
}
__device__ __forceinline__ void cpa16(u32 d, const void* s) {
    asm volatile("cp.async.ca.shared.global [%0], [%1], 16;" :: "r"(d), "l"(s));
}
__device__ __forceinline__ void cpa16z(u32 d, const void* s, int sz) {
    asm volatile("cp.async.ca.shared.global [%0], [%1], 16, %2;"
                 :: "r"(d), "l"(s), "r"(sz));
}
__device__ __forceinline__ void cp_commit() {
    asm volatile("cp.async.commit_group;" ::: "memory");
}

// ---------------- RoPE table ----------------
__global__ __launch_bounds__(256) void rope_table()
{
    int i = blockIdx.x * 256 + threadIdx.x;
    if (i >= S_ * 16) return;
    int s = i >> 4, t = i & 15;
    double inv = pow(10000.0, -(double)(2 * t) / (double)DHR);
    double ang = (double)s * inv;
    g_rope[i] = make_float2((float)cos(ang), (float)sin(ang));
}

// ---------------- merged split ----------------
#define NSPLIT 9
struct SplitArgs {
    const float* src[NSPLIT];
    u16* dh[NSPLIT];
    u16* dl[NSPLIT];
    int  n4[NSPLIT];
    int  cumblk[NSPLIT + 1];
};

__global__ __launch_bounds__(256) void splitall(SplitArgs a)
{
    int blk = blockIdx.x;
    int r = 0;
    #pragma unroll
    for (int i = 1; i < NSPLIT; i++) if (blk >= a.cumblk[i]) r = i;
    int i4 = (blk - a.cumblk[r]) * 256 + threadIdx.x;
    if (i4 >= a.n4[r]) return;
    float4 v = ((const float4*)a.src[r])[i4];
    u32 h0, l0, h1, l1;
    split_pack(v.x, v.y, h0, l0);
    split_pack(v.z, v.w, h1, l1);
    ((uint2*)a.dh[r])[i4] = make_uint2(h0, h1);
    ((uint2*)a.dl[r])[i4] = make_uint2(l0, l1);
}

// ---------------- epilogue store modes ----------------
__device__ __forceinline__ void store_region(
    int mode, float v0, float v1, int r0, int col,
    float* F, u16* Hp, u16* Lp, int ld)
{
    if (mode == 0) {
        *(float2*)&F[(size_t)r0 * ld + col] = make_float2(v0, v1);
    } else if (mode == 1) {
        u32 h, l;
        split_pack(v0, v1, h, l);
        *(u32*)&Hp[(size_t)r0 * ld + col] = h;
        *(u32*)&Lp[(size_t)r0 * ld + col] = l;
    } else {
        const int b = r0 >> 11, s = r0 & 2047;
        if (mode == 2) {
            int hh = col >> 6, d = col & 63;
            size_t dst = ((size_t)(b * H_ + hh) * S_ + s) * DQK + d;
            u32 h, l;
            split_pack(v0, v1, h, l);
            *(u32*)&Hp[dst] = h;
            *(u32*)&Lp[dst] = l;
        } else if (mode == 3) {
            int hh = col >> 5, t2 = col & 31;
            float2 cs = g_rope[s * 16 + (t2 >> 1)];
            float o0 = v0 * cs.x - v1 * cs.y;
            float o1 = v0 * cs.y + v1 * cs.x;
            size_t dst = ((size_t)(b * H_ + hh) * S_ + s) * DQK + DH + t2;
            u32 h, l;
            split_pack(o0, o1, h, l);
            *(u32*)&Hp[dst] = h;
            *(u32*)&Lp[dst] = l;
        } else {
            float2 cs = g_rope[s * 16 + (col >> 1)];
            float o0 = v0 * cs.x - v1 * cs.y;
            float o1 = v0 * cs.y + v1 * cs.x;
            u32 h, l;
            split_pack(o0, o1, h, l);
            #pragma unroll
            for (int hh = 0; hh < H_; hh++) {
                size_t dst = ((size_t)(b * H_ + hh) * S_ + s) * DQK + DH + col;
                *(u32*)&Hp[dst] = h;
                *(u32*)&Lp[dst] = l;
            }
        }
    }
}

// ---------------- split-bf16 GEMM (128x128, 2 CTA/SM) ----------------------
#define GBM 128
#define GBN 128
#define GBK 32
#define GP  40
#define GT  (GBM*GP)
#define GSTAGE (4*GT)
#define GEMM_DSMEM (2*GSTAGE*2)

__global__ __launch_bounds__(256, 2) void gemm_cp(
    const u16* __restrict__ Ah, const u16* __restrict__ Al, int lda,
    const u16* __restrict__ Bh, const u16* __restrict__ Bl,
    int mode0, float* F0, u16* H0, u16* L0, int ld0,
    int mode1, float* F1, u16* H1, u16* L1, int ld1,
    int NS, int M, int N, int K)
{
    extern __shared__ __align__(16) u16 gsm[];
    const int tid = threadIdx.x, lane = tid & 31, wid = tid >> 5;
    const int bm = blockIdx.y * GBM, bn = blockIdx.x * GBN;
    const int wm = (wid & 3) * 32, wn = (wid >> 2) * 64;
    const int g = lane >> 2, t = lane & 3;
    const int nst = K / GBK;

    float acc[2][8][4];
    #pragma unroll
    for (int mi = 0; mi < 2; mi++)
        #pragma unroll
        for (int nj = 0; nj < 8; nj++)
            #pragma unroll
            for (int c = 0; c < 4; c++) acc[mi][nj][c] = 0.f;

    auto load_stage = [&](int s) {
        u16* sb = gsm + (s & 1) * GSTAGE;
        const int k0 = s * GBK;
        #pragma unroll
        for (int i = tid; i < 512; i += 256) {
            int r = i >> 2, c = i & 3;
            int so = r * GP + c * 8;
            size_t ga = (size_t)(bm + r) * lda + k0 + c * 8;
            cpa16(sptr(sb + so),      Ah + ga);
            cpa16(sptr(sb + GT + so), Al + ga);
            int br = bn + r;
            int ok = (br < N) ? 16 : 0;
            size_t gb = (size_t)(ok ? br : 0) * K + k0 + c * 8;
            cpa16z(sptr(sb + 2*GT + so), Bh + gb, ok);
            cpa16z(sptr(sb + 3*GT + so), Bl + gb, ok);
        }
        cp_commit();
    };

    load_stage(0);
    if (nst > 1) load_stage(1);

    for (int s = 0; s < nst; s++) {
        if (s + 1 < nst) asm volatile("cp.async.wait_group 1;" ::: "memory");
        else             asm volatile("cp.async.wait_group 0;" ::: "memory");
        __syncthreads();

        u16* sb = gsm + (s & 1) * GSTAGE;
        #pragma unroll
        for (int kk = 0; kk < GBK; kk += 16) {
            u32 a[2][2][4];
            #pragma unroll
            for (int mi = 0; mi < 2; mi++) {
                int row = wm + mi * 16 + (lane & 15), col = kk + (lane >> 4) * 8;
                ldmx4(a[0][mi], sptr(sb + row*GP + col));
                ldmx4(a[1][mi], sptr(sb + GT + row*GP + col));
            }
            u32 bh[4][4], bl[4][4];
            #pragma unroll
            for (int ng = 0; ng < 4; ng++) {
                int row = wn + ng * 16 + (lane & 15), col = kk + (lane >> 4) * 8;
                ldmx4(bh[ng], sptr(sb + 2*GT + row*GP + col));
                ldmx4(bl[ng], sptr(sb + 3*GT + row*GP + col));
            }
            #pragma unroll
            for (int ng = 0; ng < 4; ng++)
                #pragma unroll
                for (int mi = 0; mi < 2; mi++) {
                    mma16816(acc[mi][2*ng],   a[0][mi], bh[ng][0], bh[ng][2]);
                    mma16816(acc[mi][2*ng+1], a[0][mi], bh[ng][1], bh[ng][3]);
                }
            #pragma unroll
            for (int ng = 0; ng < 4; ng++)
                #pragma unroll
                for (int mi = 0; mi < 2; mi++) {
                    mma16816(acc[mi][2*ng],   a[0][mi], bl[ng][0], bl[ng][2]);
                    mma16816(acc[mi][2*ng+1], a[0][mi], bl[ng][1], bl[ng][3]);
                }
            #pragma unroll
            for (int ng = 0; ng < 4; ng++)
                #pragma unroll
                for (int mi = 0; mi < 2; mi++) {
                    mma16816(acc[mi][2*ng],   a[1][mi], bh[ng][0], bh[ng][2]);
                    mma16816(acc[mi][2*ng+1], a[1][mi], bh[ng][1], bh[ng][3]);
                }
        }
        __syncthreads();
        if (s + 2 < nst) load_stage(s + 2);
    }

    #pragma unroll
    for (int mi = 0; mi < 2; mi++) {
        int r0 = bm + wm + mi * 16 + g;
        #pragma unroll
        for (int nj = 0; nj < 8; nj++) {
            int col = bn + wn + nj * 8 + t * 2;
            if (col >= N) continue;
            float v0 = acc[mi][nj][0], v1 = acc[mi][nj][1];
            float w0 = acc[mi][nj][2], w1 = acc[mi][nj][3];
            if (col < NS) {
                store_region(mode0, v0, v1, r0,     col, F0, H0, L0, ld0);
                store_region(mode0, w0, w1, r0 + 8, col, F0, H0, L0, ld0);
            } else {
                store_region(mode1, v0, v1, r0,     col - NS, F1, H1, L1, ld1);
                store_region(mode1, w0, w1, r0 + 8, col - NS, F1, H1, L1, ld1);
            }
        }
    }
}

// ---------------- flash attention (merged grid, log2 softmax) --------------
#define FBQ 256
#define FBK 64
#define QKP 104
#define VP  72
#define KVST (2*64*QKP + 2*64*VP)
#define FQ_U16 (2*FBQ*QKP)
#define FLASH_SMEM_U16 (FQ_U16 + 2*KVST)
#define FLASH_SMEM_BYTES (FLASH_SMEM_U16 * 2)

__global__ __launch_bounds__(512, 1) void flash_mma(
    const u16* __restrict__ Qh, const u16* __restrict__ Ql,
    const u16* __restrict__ Kh, const u16* __restrict__ Kl,
    const u16* __restrict__ Vh, const u16* __restrict__ Vl,
    u16* __restrict__ Oh, u16* __restrict__ Ol)
{
    extern __shared__ __align__(16) u16 smf[];
    u16* Qsh = smf;
    u16* Qsl = smf + FBQ*QKP;

    const int bh = blockIdx.y, b = bh / H_, h = bh % H_;
    const int qb = gridDim.x - 1 - blockIdx.x;
    const int q0 = qb * FBQ;
    const int tid = threadIdx.x, w = tid >> 5, lane = tid & 31;
    const int g = lane >> 2, t = lane & 3;

    auto load_kv = [&](int kb) {
        u16* st = smf + FQ_U16 + (kb & 1) * KVST;
        const size_t kbase = ((size_t)bh * S_ + kb * FBK) * DQK;
        for (int c = tid; c < 64 * 12; c += 512) {
            int r = c / 12, s = c % 12;
            const size_t go = kbase + (size_t)r * DQK + s * 8;
            cpa16(sptr(st + r*QKP + s*8),            Kh + go);
            cpa16(sptr(st + 64*QKP + r*QKP + s*8),   Kl + go);
        }
        for (int c = tid; c < 64 * 8; c += 512) {
            int r = c >> 3, s = c & 7;
            size_t gv = ((size_t)(b * S_ + kb * FBK + r)) * D_ + h * DH + s * 8;
            cpa16(sptr(st + 2*64*QKP + r*VP + s*8),          Vh + gv);
            cpa16(sptr(st + 2*64*QKP + 64*VP + r*VP + s*8),  Vl + gv);
        }
        cp_commit();
    };

    {
        const size_t qbase = ((size_t)bh * S_ + q0) * DQK;
        for (int c = tid; c < FBQ * 12; c += 512) {
            int r = c / 12, s = c % 12;
            const size_t go = qbase + (size_t)r * DQK + s * 8;
            cpa16(sptr(Qsh + r*QKP + s*8), Qh + go);
            cpa16(sptr(Qsl + r*QKP + s*8), Ql + go);
        }
        load_kv(0);
    }

    float acco[8][4];
    #pragma unroll
    for (int j = 0; j < 8; j++)
        #pragma unroll
        for (int c = 0; c < 4; c++) acco[j][c] = 0.f;
    float mstate[2] = {-INFINITY, -INFINITY};
    float lstate[2] = {0.f, 0.f};
    const float scl2 = rsqrtf(96.f) * 1.4426950408889634f;
    const int qiA = q0 + w * 16 + g;
    const int qiB = qiA + 8;

    const int nkb = (q0 + FBQ) / FBK;
    for (int kb = 0; kb < nkb; kb++) {
        if (kb + 1 < nkb) {
            load_kv(kb + 1);
            asm volatile("cp.async.wait_group 1;" ::: "memory");
        } else {
            asm volatile("cp.async.wait_group 0;" ::: "memory");
        }
        __syncthreads();

        u16* st  = smf + FQ_U16 + (kb & 1) * KVST;
        u16* Ksh = st;
        u16* Ksl = st + 64*QKP;
        u16* Vsh = st + 2*64*QKP;
        u16* Vsl = st + 2*64*QKP + 64*VP;
        const int k0 = kb * FBK;

        const bool active = (k0 <= q0 + w * 16 + 15);
        if (active) {
            float sc[8][4];
            #pragma unroll
            for (int j = 0; j < 8; j++)
                #pragma unroll
                for (int c = 0; c < 4; c++) sc[j][c] = 0.f;

            #pragma unroll
            for (int kc = 0; kc < 6; kc++) {
                u32 ah[4], al[4];
                {
                    int row = w * 16 + (lane & 15), col = kc * 16 + (lane >> 4) * 8;
                    ldmx4(ah, sptr(&Qsh[row*QKP + col]));
                    ldmx4(al, sptr(&Qsl[row*QKP + col]));
                }
                u32 kh[4][4], kl[4][4];
                #pragma unroll
                for (int ng = 0; ng < 4; ng++) {
                    int row = ng * 16 + (lane & 15), col = kc * 16 + (lane >> 4) * 8;
                    ldmx4(kh[ng], sptr(&Ksh[row*QKP + col]));
                    ldmx4(kl[ng], sptr(&Ksl[row*QKP + col]));
                }
                #pragma unroll
                for (int ng = 0; ng < 4; ng++) {
                    mma16816(sc[2*ng],   ah, kh[ng][0], kh[ng][2]);
                    mma16816(sc[2*ng+1], ah, kh[ng][1], kh[ng][3]);
                }
                #pragma unroll
                for (int ng = 0; ng < 4; ng++) {
                    mma16816(sc[2*ng],   ah, kl[ng][0], kl[ng][2]);
                    mma16816(sc[2*ng+1], ah, kl[ng][1], kl[ng][3]);
                }
                #pragma unroll
                for (int ng = 0; ng < 4; ng++) {
                    mma16816(sc[2*ng],   al, kh[ng][0], kh[ng][2]);
                    mma16816(sc[2*ng+1], al, kh[ng][1], kh[ng][3]);
                }
            }

            const bool diag = (k0 + FBK - 1 > q0 + w * 16);
            #pragma unroll
            for (int j = 0; j < 8; j++) {
                int kcol = k0 + j * 8 + t * 2;
                #pragma unroll
                for (int c = 0; c < 4; c++) {
                    int ki = kcol + (c & 1);
                    int qi = (c < 2) ? qiA : qiB;
                    float v = fminf(fmaxf(sc[j][c], -80.f), 80.f) * scl2;
                    sc[j][c] = (!diag || ki <= qi) ? v : -INFINITY;
                }
            }

            float mA = -INFINITY, mB = -INFINITY;
            #pragma unroll
            for (int j = 0; j < 8; j++) {
                mA = fmaxf(mA, fmaxf(sc[j][0], sc[j][1]));
                mB = fmaxf(mB, fmaxf(sc[j][2], sc[j][3]));
            }
            mA = fmaxf(mA, __shfl_xor_sync(0xffffffffu, mA, 1));
            mA = fmaxf(mA, __shfl_xor_sync(0xffffffffu, mA, 2));
            mB = fmaxf(mB, __shfl_xor_sync(0xffffffffu, mB, 1));
            mB = fmaxf(mB, __shfl_xor_sync(0xffffffffu, mB, 2));
            float mnA = fmaxf(mstate[0], mA), mnB = fmaxf(mstate[1], mB);
            float corrA = exp2f(mstate[0] - mnA);
            float corrB = exp2f(mstate[1] - mnB);
            float sumA = 0.f, sumB = 0.f;
            #pragma unroll
            for (int j = 0; j < 8; j++) {
                sc[j][0] = exp2f(sc[j][0] - mnA); sumA += sc[j][0];
                sc[j][1] = exp2f(sc[j][1] - mnA); sumA += sc[j][1];
                sc[j][2] = exp2f(sc[j][2] - mnB); sumB += sc[j][2];
                sc[j][3] = exp2f(sc[j][3] - mnB); sumB += sc[j][3];
            }
            sumA += __shfl_xor_sync(0xffffffffu, sumA, 1);
            sumA += __shfl_xor_sync(0xffffffffu, sumA, 2);
            sumB += __shfl_xor_sync(0xffffffffu, sumB, 1);
            sumB += __shfl_xor_sync(0xffffffffu, sumB, 2);
            lstate[0] = lstate[0] * corrA + sumA;
            lstate[1] = lstate[1] * corrB + sumB;
            mstate[0] = mnA; mstate[1] = mnB;
            #pragma unroll
            for (int vj = 0; vj < 8; vj++) {
                acco[vj][0] *= corrA; acco[vj][1] *= corrA;
                acco[vj][2] *= corrB; acco[vj][3] *= corrB;
            }

            #pragma unroll
            for (int kcp = 0; kcp < 4; kcp++) {
                u32 ph[4], pl[4];
                split_pack(sc[2*kcp  ][0], sc[2*kcp  ][1], ph[0], pl[0]);
                split_pack(sc[2*kcp  ][2], sc[2*kcp  ][3], ph[1], pl[1]);
                split_pack(sc[2*kcp+1][0], sc[2*kcp+1][1], ph[2], pl[2]);
                split_pack(sc[2*kcp+1][2], sc[2*kcp+1][3], ph[3], pl[3]);
                u32 vhf[4][4], vlf[4][4];
                #pragma unroll
                for (int vg = 0; vg < 4; vg++) {
                    int row = kcp * 16 + (lane & 15), col = vg * 16 + (lane >> 4) * 8;
                    ldmx4t(vhf[vg], sptr(&Vsh[row*VP + col]));
                    ldmx4t(vlf[vg], sptr(&Vsl[row*VP + col]));
                }
                #pragma unroll
                for (int vg = 0; vg < 4; vg++) {
                    mma16816(acco[2*vg],   ph, vhf[vg][0], vhf[vg][1]);
                    mma16816(acco[2*vg+1], ph, vhf[vg][2], vhf[vg][3]);
                }
                #pragma unroll
                for (int vg = 0; vg < 4; vg++) {
                    mma16816(acco[2*vg],   ph, vlf[vg][0], vlf[vg][1]);
                    mma16816(acco[2*vg+1], ph, vlf[vg][2], vlf[vg][3]);
                }
                #pragma unroll
                for (int vg = 0; vg < 4; vg++) {
                    mma16816(acco[2*vg],   pl, vhf[vg][0], vhf[vg][1]);
                    mma16816(acco[2*vg+1], pl, vhf[vg][2], vhf[vg][3]);
                }
            }
        }
        __syncthreads();
    }

    float ilA = 1.f / lstate[0], ilB = 1.f / lstate[1];
    int rA = b * S_ + q0 + w * 16 + g;
    #pragma unroll
    for (int vj = 0; vj < 8; vj++) {
        int col = h * DH + vj * 8 + t * 2;
        u32 h0, l0, h1, l1;
        split_pack(acco[vj][0] * ilA, acco[vj][1] * ilA, h0, l0);
        split_pack(acco[vj][2] * ilB, acco[vj][3] * ilB, h1, l1);
        *(u32*)&Oh[(size_t)rA * D_ + col] = h0;
        *(u32*)&Ol[(size_t)rA * D_ + col] = l0;
        *(u32*)&Oh[(size_t)(rA+8) * D_ + col] = h1;
        *(u32*)&Ol[(size_t)(rA+8) * D_ + col] = l1;
    }
}

// ---------------- launch ----------------
extern "C" void kernel_launch(void* const* d_in, const int* in_sizes, int n_in,
                              void* d_out, int out_size)
{
    const float* x     = (const float*)d_in[0];
    const float* W_DQ  = (const float*)d_in[1];
    const float* W_UQ  = (const float*)d_in[2];
    const float* W_QR  = (const float*)d_in[3];
    const float* W_DKV = (const float*)d_in[4];
    const float* W_UK  = (const float*)d_in[5];
    const float* W_UV  = (const float*)d_in[6];
    const float* W_KR  = (const float*)d_in[7];
    const float* W_O   = (const float*)d_in[8];
    float* out = (float*)d_out;

    u16 *xh,*xl,*wh,*wl,*ch,*cl,*vh,*vl,*qh,*ql,*kh,*kl,*ah,*al;
    cudaGetSymbolAddress((void**)&xh, g_xh);    cudaGetSymbolAddress((void**)&xl, g_xl);
    cudaGetSymbolAddress((void**)&wh, g_wh);    cudaGetSymbolAddress((void**)&wl, g_wl);
    cudaGetSymbolAddress((void**)&ch, g_cQKVh); cudaGetSymbolAddress((void**)&cl, g_cQKVl);
    cudaGetSymbolAddress((void**)&vh, g_vh);    cudaGetSymbolAddress((void**)&vl, g_vl);
    cudaGetSymbolAddress((void**)&qh, g_qh);    cudaGetSymbolAddress((void**)&ql, g_ql);
    cudaGetSymbolAddress((void**)&kh, g_kh);    cudaGetSymbolAddress((void**)&kl, g_kl);
    cudaGetSymbolAddress((void**)&ah, g_ah);    cudaGetSymbolAddress((void**)&al, g_al);

    static cudaStream_t s2 = nullptr;
    static cudaEvent_t evFork = nullptr, evJoin = nullptr;
    static int configured = 0;
    if (!configured) {
        cudaFuncSetAttribute(flash_mma, cudaFuncAttributeMaxDynamicSharedMemorySize,
                             FLASH_SMEM_BYTES);
        cudaFuncSetAttribute(gemm_cp, cudaFuncAttributeMaxDynamicSharedMemorySize,
                             GEMM_DSMEM);
        cudaStreamCreateWithFlags(&s2, cudaStreamNonBlocking);
        cudaEventCreateWithFlags(&evFork, cudaEventDisableTiming);
        cudaEventCreateWithFlags(&evJoin, cudaEventDisableTiming);
        configured = 1;
    }

    SplitArgs sa;
    {
        const float* srcs[NSPLIT] = {x, W_DQ, W_DKV, W_KR, W_UQ, W_QR, W_UK, W_UV, W_O};
        u16* dhs[NSPLIT] = {xh, wh+OFF_DOWN, wh+OFF_DOWN+524288, wh+OFF_DOWN+1048576,
                            wh+OFF_UQQR, wh+OFF_UQQR+524288,
                            wh+OFF_UKUV, wh+OFF_UKUV+524288, wh+OFF_WO};
        u16* dls[NSPLIT] = {xl, wl+OFF_DOWN, wl+OFF_DOWN+524288, wl+OFF_DOWN+1048576,
                            wl+OFF_UQQR, wl+OFF_UQQR+524288,
                            wl+OFF_UKUV, wl+OFF_UKUV+524288, wl+OFF_WO};
        const int ns[NSPLIT] = {MS*D_, DLAT*D_, DLAT*D_, DHR*D_,
                                D_*DLAT, H_*DHR*DLAT, D_*DLAT, D_*DLAT, D_*D_};
        int cum = 0;
        for (int i = 0; i < NSPLIT; i++) {
            sa.src[i] = srcs[i]; sa.dh[i] = dhs[i]; sa.dl[i] = dls[i];
            sa.n4[i] = ns[i] / 4;
            sa.cumblk[i] = cum;
            cum += (sa.n4[i] + 255) / 256;
        }
        sa.cumblk[NSPLIT] = cum;
        splitall<<<cum, 256>>>(sa);
    }

    rope_table<<<(S_ * 16 + 255) / 256, 256>>>();

    auto gemm = [&](cudaStream_t st,
                    const u16* Ahp, const u16* Alp, int lda,
                    const u16* Bhp, const u16* Blp,
                    int m0, float* F0, u16* H0, u16* L0, int ld0,
                    int m1, float* F1, u16* H1, u16* L1, int ld1,
                    int NSv, int M, int N, int K) {
        gemm_cp<<<dim3((N + GBN - 1) / GBN, M / GBM), 256, GEMM_DSMEM, st>>>(
            Ahp, Alp, lda, Bhp, Blp, m0, F0, H0, L0, ld0,
            m1, F1, H1, L1, ld1, NSv, M, N, K);
    };

    // DOWN (x -> cQKV, KR+rope -> k) on main
    gemm(0, xh, xl, D_, wh+OFF_DOWN, wl+OFF_DOWN,
         1, nullptr, ch, cl, D_,
         4, nullptr, kh, kl, 0,
         D_, MS, D_ + DHR, D_);

    // fork: UQQR on s2, UKUV on main (concurrent)
    cudaEventRecord(evFork, 0);
    cudaStreamWaitEvent(s2, evFork, 0);

    // UK+UV (cKV -> kC scatter, v) — profiled slot (launch idx 5)
    gemm(0, ch + DLAT, cl + DLAT, D_, wh+OFF_UKUV, wl+OFF_UKUV,
         2, nullptr, kh, kl, 0,
         1, nullptr, vh, vl, D_,
         D_, MS, 2 * D_, DLAT);

    gemm(s2, ch, cl, D_, wh+OFF_UQQR, wl+OFF_UQQR,
         2, nullptr, qh, ql, 0,
         3, nullptr, qh, ql, 0,
         D_, MS, D_ + H_ * DHR, DLAT);

    cudaEventRecord(evJoin, s2);
    cudaStreamWaitEvent(0, evJoin, 0);

    flash_mma<<<dim3(S_ / FBQ, B_ * H_), dim3(512), FLASH_SMEM_BYTES>>>(
        qh, ql, kh, kl, vh, vl, ah, al);

    gemm(0, ah, al, D_, wh+OFF_WO, wl+OFF_WO,
         0, out, nullptr, nullptr, D_,
         0, out, nullptr, nullptr, D_,
         D_, MS, D_, D_);
}